// round 1
// baseline (speedup 1.0000x reference)
#include <cuda_runtime.h>
#include <math.h>

#define NN 200000
#define EE 1000000
#define INF 128
#define OUTF 128
#define HH 4
#define DKK 32

// ---------------- scratch (device globals; no allocation) ----------------
// Ktr & Mtr interleaved per node for gather locality: [2][N][2][128]
__device__ float g_KM [(size_t)2*NN*2*OUTF];   // 409.6 MB
__device__ float g_Q  [(size_t)2*NN*OUTF];     // 204.8 MB
__device__ float g_agg[(size_t)2*NN*OUTF];     // 204.8 MB
__device__ float g_den[(size_t)2*NN*HH];       // 6.4 MB
__device__ float g_WkA[2*INF*OUTF];
__device__ float g_bkA[2*OUTF];
__device__ float g_WmM[2*INF*OUTF];
__device__ float g_bmM[2*OUTF];

// ---------------- prep: fold w_att/w_msg (+ mu*scale) into projection weights
__global__ void prep_kernel(const float* __restrict__ Wk, const float* __restrict__ bk,
                            const float* __restrict__ Wm, const float* __restrict__ bm,
                            const float* __restrict__ w_att, const float* __restrict__ w_msg,
                            const float* __restrict__ mu) {
    int idx = blockIdx.x*blockDim.x + threadIdx.x;     // [0, 2*2*128*128)
    const int total = 2*INF*OUTF;
    int m   = idx / total;          // 0: K·w_att, 1: M·w_msg
    int rem = idx - m*total;
    int t   = rem / (INF*OUTF);
    int io  = rem - t*(INF*OUTF);
    int i   = io / OUTF;
    int o   = io - i*OUTF;
    int h   = o >> 5, f = o & 31;

    const float* W = m ? Wm : Wk;
    const float* R = m ? w_msg : w_att;
    const float* wrow = W + ((size_t)t*INF + i)*OUTF + h*DKK;
    const float* rr   = R + (((size_t)t*HH + h)*DKK)*DKK + f;
    float s = 0.f;
    #pragma unroll
    for (int d = 0; d < DKK; d++) s += wrow[d] * rr[(size_t)d*DKK];
    float fold = m ? 1.f : mu[t*HH + h] * 0.17677669529663687f;  // mu * 1/sqrt(DK)
    (m ? g_WmM : g_WkA)[(size_t)t*INF*OUTF + io] = s * fold;

    if (i == 0) {  // fold bias through the relation matrix too
        const float* b = m ? bm : bk;
        float sb = 0.f;
        #pragma unroll
        for (int d = 0; d < DKK; d++) sb += b[t*OUTF + h*DKK + d] * rr[(size_t)d*DKK];
        (m ? g_bmM : g_bkA)[t*OUTF + o] = sb * fold;
    }
}

// ---------------- zero agg + den ----------------
__global__ void zero_kernel() {
    size_t i = (size_t)blockIdx.x*blockDim.x + threadIdx.x;
    const size_t n4 = (size_t)2*NN*OUTF/4;
    if (i < n4) ((float4*)g_agg)[i] = make_float4(0.f,0.f,0.f,0.f);
    if (i < (size_t)2*NN*HH) g_den[i] = 0.f;
}

// ---------------- fused projections: Ktr, Mtr, Q ----------------
__global__ void __launch_bounds__(128) proj_kernel(const float* __restrict__ x,
                                                   const float* __restrict__ Wq,
                                                   const float* __restrict__ bq) {
    __shared__ float xs[32][INF];
    __shared__ float ws[16][OUTF];
    int tid  = threadIdx.x;
    int base = blockIdx.x * 32;      // global node row in [0, 2N)
    int nt   = base >= NN;

    const float* xrow = x + (size_t)base*INF;
    #pragma unroll 4
    for (int r = 0; r < 32; r++) xs[r][tid] = xrow[(size_t)r*INF + tid];
    __syncthreads();

    for (int m = 0; m < 3; m++) {
        const float* W = (m==0) ? g_WkA + (size_t)nt*INF*OUTF
                       : (m==1) ? g_WmM + (size_t)nt*INF*OUTF
                                : Wq    + (size_t)nt*INF*OUTF;
        const float* B = (m==0) ? g_bkA + nt*OUTF
                       : (m==1) ? g_bmM + nt*OUTF
                                : bq    + nt*OUTF;
        float acc[32];
        float bb = B[tid];
        #pragma unroll
        for (int r = 0; r < 32; r++) acc[r] = bb;

        for (int kk = 0; kk < INF; kk += 16) {
            #pragma unroll
            for (int i = 0; i < 16; i++) ws[i][tid] = W[(size_t)(kk+i)*OUTF + tid];
            __syncthreads();
            #pragma unroll
            for (int i = 0; i < 16; i++) {
                float wv = ws[i][tid];
                float xv;
                #pragma unroll
                for (int r = 0; r < 32; r++) {
                    xv = xs[r][kk+i];
                    acc[r] = fmaf(xv, wv, acc[r]);
                }
            }
            __syncthreads();
        }
        if (m == 2) {
            #pragma unroll 4
            for (int r = 0; r < 32; r++)
                g_Q[(size_t)(base+r)*OUTF + tid] = acc[r];
        } else {
            #pragma unroll 4
            for (int r = 0; r < 32; r++)
                g_KM[((size_t)(base+r)*2 + m)*OUTF + tid] = acc[r];
        }
    }
}

// ---------------- edge pass: att + exp + weighted message scatter ----------------
__global__ void __launch_bounds__(256) edge_kernel(const int* __restrict__ ei) {
    int warp = (blockIdx.x*blockDim.x + threadIdx.x) >> 5;
    int lane = threadIdx.x & 31;
    if (warp >= 2*EE) return;
    int t = (warp >= EE);
    int e = warp - t*EE;
    // EDGE_META: src type = t, dst type = 1-t
    int src = ei[(size_t)t*2*EE + e];
    int dst = ei[(size_t)t*2*EE + EE + e];
    int s = t, d = 1 - t;

    const float4* kq = (const float4*)(g_KM + ((size_t)(s*NN + src)*2)*OUTF);
    const float4* qp = (const float4*)(g_Q  +  (size_t)(d*NN + dst)*OUTF);
    float4 k4 = kq[lane];
    float4 q4 = qp[lane];
    float p = k4.x*q4.x + k4.y*q4.y + k4.z*q4.z + k4.w*q4.w;
    // reduce within 8-lane head group, broadcast
    p += __shfl_down_sync(0xffffffffu, p, 4, 8);
    p += __shfl_down_sync(0xffffffffu, p, 2, 8);
    p += __shfl_down_sync(0xffffffffu, p, 1, 8);
    float att = __shfl_sync(0xffffffffu, p, 0, 8);
    float ev  = __expf(att);   // mu*scale pre-folded; no max needed (att ~ N(0,1))

    const float4* mp = (const float4*)(g_KM + ((size_t)(s*NN + src)*2 + 1)*OUTF);
    float4 m4 = mp[lane];

    float* arow = g_agg + (size_t)(d*NN + dst)*OUTF + lane*4;
    asm volatile("red.global.add.v4.f32 [%0], {%1,%2,%3,%4};"
                 :: "l"(arow), "f"(m4.x*ev), "f"(m4.y*ev), "f"(m4.z*ev), "f"(m4.w*ev)
                 : "memory");
    if ((lane & 7) == 0)
        atomicAdd(g_den + (size_t)(d*NN + dst)*HH + (lane >> 3), ev);
}

// ---------------- node pass: normalize, gelu, @Wa+ba, skip blend, layernorm ----
__global__ void __launch_bounds__(128) node_kernel(const float* __restrict__ x,
                                                   const float* __restrict__ Wa,
                                                   const float* __restrict__ ba,
                                                   const float* __restrict__ skip,
                                                   const float* __restrict__ lns,
                                                   const float* __restrict__ lnb,
                                                   float* __restrict__ out) {
    __shared__ float G[32][OUTF];
    __shared__ float ws[16][OUTF];
    int tid  = threadIdx.x;
    int base = blockIdx.x * 32;
    int nt   = base >= NN;
    int hcol = tid >> 5;     // head owning column tid

    // stage A: softmax normalize + exact gelu
    #pragma unroll 2
    for (int r = 0; r < 32; r++) {
        size_t node = (size_t)(base + r);
        float a  = g_agg[node*OUTF + tid];
        float dn = g_den[node*HH + hcol];
        float v  = a / (dn + 1e-16f);
        G[r][tid] = 0.5f * v * (1.0f + erff(v * 0.70710678118654752f));
    }
    __syncthreads();

    // stage B: [32,128] @ Wa[nt]
    const float* W = Wa + (size_t)nt*OUTF*OUTF;
    float acc[32];
    float bb = ba[nt*OUTF + tid];
    #pragma unroll
    for (int r = 0; r < 32; r++) acc[r] = bb;
    for (int kk = 0; kk < OUTF; kk += 16) {
        #pragma unroll
        for (int i = 0; i < 16; i++) ws[i][tid] = W[(size_t)(kk+i)*OUTF + tid];
        __syncthreads();
        #pragma unroll
        for (int i = 0; i < 16; i++) {
            float wv = ws[i][tid];
            #pragma unroll
            for (int r = 0; r < 32; r++) acc[r] = fmaf(G[r][kk+i], wv, acc[r]);
        }
        __syncthreads();
    }

    // stage C: skip blend -> smem
    float alpha = 1.f / (1.f + __expf(-skip[nt]));
    #pragma unroll 2
    for (int r = 0; r < 32; r++) {
        size_t node = (size_t)(base + r);
        float xv = x[node*INF + tid];
        G[r][tid] = alpha*acc[r] + (1.f - alpha)*xv;
    }
    __syncthreads();

    // stage D: layernorm, warp w handles rows 8w..8w+7
    int wid = tid >> 5, lane = tid & 31;
    for (int rr = 0; rr < 8; rr++) {
        int r = wid*8 + rr;
        float s1 = 0.f, s2 = 0.f;
        #pragma unroll
        for (int c = lane; c < OUTF; c += 32) { float v = G[r][c]; s1 += v; s2 += v*v; }
        #pragma unroll
        for (int off = 16; off; off >>= 1) {
            s1 += __shfl_xor_sync(0xffffffffu, s1, off);
            s2 += __shfl_xor_sync(0xffffffffu, s2, off);
        }
        float mean = s1 * (1.f/OUTF);
        float var  = s2 * (1.f/OUTF) - mean*mean;
        float inv  = rsqrtf(var + 1e-5f);
        size_t node = (size_t)(base + r);
        #pragma unroll
        for (int c = lane; c < OUTF; c += 32)
            out[node*OUTF + c] = (G[r][c] - mean)*inv*lns[nt*OUTF + c] + lnb[nt*OUTF + c];
    }
}

// ---------------- launch ----------------
extern "C" void kernel_launch(void* const* d_in, const int* in_sizes, int n_in,
                              void* d_out, int out_size) {
    const float* x     = (const float*)d_in[0];
    const int*   ei    = (const int*)  d_in[1];
    const float* Wk    = (const float*)d_in[2];
    const float* bk    = (const float*)d_in[3];
    const float* Wq    = (const float*)d_in[4];
    const float* bq    = (const float*)d_in[5];
    const float* Wm    = (const float*)d_in[6];
    const float* bm    = (const float*)d_in[7];
    const float* Wa    = (const float*)d_in[8];
    const float* ba    = (const float*)d_in[9];
    const float* w_att = (const float*)d_in[10];
    const float* w_msg = (const float*)d_in[11];
    const float* mu    = (const float*)d_in[12];
    const float* skip  = (const float*)d_in[13];
    const float* lns   = (const float*)d_in[14];
    const float* lnb   = (const float*)d_in[15];
    float* out = (float*)d_out;

    prep_kernel<<<256, 256>>>(Wk, bk, Wm, bm, w_att, w_msg, mu);
    zero_kernel<<<50000, 256>>>();
    proj_kernel<<<(2*NN)/32, 128>>>(x, Wq, bq);
    edge_kernel<<<(2*EE*32)/256, 256>>>(ei);
    node_kernel<<<(2*NN)/32, 128>>>(x, Wa, ba, skip, lns, lnb, out);
}

// round 3
// speedup vs baseline: 2.0714x; 2.0714x over previous
#include <cuda_runtime.h>
#include <cuda_bf16.h>
#include <math.h>
#include <stdint.h>

#define NN 200000
#define EE 1000000
#define INF 128
#define OUTF 128
#define HH 4
#define DKK 32
#define TILES 1563            // ceil(NN/128)

// smem layout (bytes): A rows padded to 272B (conflict-free mma frag LDS)
#define ROWB 272
#define A_HI_OFF 0
#define A_LO_OFF 34816
#define B_HI_OFF 69632
#define B_LO_OFF 104448
#define SMEM_TOT 139264

// ---------------- scratch (device globals; no allocation) ----------------
__device__ float g_KM [(size_t)2*NN*2*OUTF];   // Ktr/Mtr interleaved [2][N][2][128]
__device__ float g_Q  [(size_t)2*NN*OUTF];
__device__ float g_agg[(size_t)2*NN*OUTF];
__device__ float g_den[(size_t)2*NN*HH];
__device__ float g_WkA[2*INF*OUTF];
__device__ float g_bkA[2*OUTF];
__device__ float g_WmM[2*INF*OUTF];
__device__ float g_bmM[2*OUTF];
// packed bf16 hi/lo weights, W^T layout [o][k]: [mat(4)][type(2)][hl(2)][128*128]
__device__ __nv_bfloat16 g_Wb[(size_t)4*2*2*16384];

#define MMA16816(acc, A0,A1,A2,A3, B0,B1) \
  asm volatile("mma.sync.aligned.m16n8k16.row.col.f32.bf16.bf16.f32 " \
    "{%0,%1,%2,%3}, {%4,%5,%6,%7}, {%8,%9}, {%0,%1,%2,%3};" \
    : "+f"((acc)[0]), "+f"((acc)[1]), "+f"((acc)[2]), "+f"((acc)[3]) \
    : "r"(A0), "r"(A1), "r"(A2), "r"(A3), "r"(B0), "r"(B1))

// ---------------- prep: fold w_att/w_msg (+ mu*scale) into projection weights
__global__ void prep_fold(const float* __restrict__ Wk, const float* __restrict__ bk,
                          const float* __restrict__ Wm, const float* __restrict__ bm,
                          const float* __restrict__ w_att, const float* __restrict__ w_msg,
                          const float* __restrict__ mu) {
    int idx = blockIdx.x*blockDim.x + threadIdx.x;     // 2*2*128*128 = 65536
    const int total = 2*INF*OUTF;
    int m   = idx / total;
    int rem = idx - m*total;
    int t   = rem / (INF*OUTF);
    int io  = rem - t*(INF*OUTF);
    int i   = io / OUTF;
    int o   = io - i*OUTF;
    int h   = o >> 5, f = o & 31;

    const float* W = m ? Wm : Wk;
    const float* R = m ? w_msg : w_att;
    const float* wrow = W + ((size_t)t*INF + i)*OUTF + h*DKK;
    const float* rr   = R + (((size_t)t*HH + h)*DKK)*DKK + f;
    float s = 0.f;
    #pragma unroll
    for (int d = 0; d < DKK; d++) s += wrow[d] * rr[(size_t)d*DKK];
    float fold = m ? 1.f : mu[t*HH + h] * 0.17677669529663687f;   // mu / sqrt(DK)
    (m ? g_WmM : g_WkA)[(size_t)t*INF*OUTF + io] = s * fold;

    if (i == 0) {
        const float* b = m ? bm : bk;
        float sb = 0.f;
        #pragma unroll
        for (int d = 0; d < DKK; d++) sb += b[t*OUTF + h*DKK + d] * rr[(size_t)d*DKK];
        (m ? g_bmM : g_bkA)[t*OUTF + o] = sb * fold;
    }
}

// pack 4 matrices (Kfold, Mfold, Q, A) per type as W^T [o][k] bf16 hi/lo
__global__ void prep_pack(const float* __restrict__ Wq, const float* __restrict__ Wa) {
    int idx = blockIdx.x*blockDim.x + threadIdx.x;   // 4*2*16384 = 131072
    int mat = idx >> 15;
    int rem = idx & 32767;
    int t   = rem >> 14;
    int ok  = rem & 16383;
    int o   = ok >> 7;
    int k   = ok & 127;
    const float* W = (mat==0) ? g_WkA : (mat==1) ? g_WmM : (mat==2) ? Wq : Wa;
    float v = W[((size_t)t*INF + k)*OUTF + o];
    __nv_bfloat16 h = __float2bfloat16(v);
    __nv_bfloat16 l = __float2bfloat16(v - __bfloat162float(h));
    size_t b = (size_t)((mat*2 + t)*2) * 16384;
    g_Wb[b + ok]         = h;
    g_Wb[b + 16384 + ok] = l;
}

// ---------------- zero agg + den ----------------
__global__ void zero_kernel() {
    size_t i = (size_t)blockIdx.x*blockDim.x + threadIdx.x;
    const size_t n4 = (size_t)2*NN*OUTF/4;
    if (i < n4) ((float4*)g_agg)[i] = make_float4(0.f,0.f,0.f,0.f);
    if (i < (size_t)2*NN*HH) g_den[i] = 0.f;
}

// split float4 -> two bf16x2 hi words + two lo words
__device__ __forceinline__ void split4(float4 v, uint32_t* hi2, uint32_t* lo2) {
    __nv_bfloat162 h01 = __floats2bfloat162_rn(v.x, v.y);
    __nv_bfloat162 h23 = __floats2bfloat162_rn(v.z, v.w);
    __nv_bfloat162 l01 = __floats2bfloat162_rn(v.x - __bfloat162float(h01.x),
                                               v.y - __bfloat162float(h01.y));
    __nv_bfloat162 l23 = __floats2bfloat162_rn(v.z - __bfloat162float(h23.x),
                                               v.w - __bfloat162float(h23.y));
    hi2[0] = *reinterpret_cast<uint32_t*>(&h01);
    hi2[1] = *reinterpret_cast<uint32_t*>(&h23);
    lo2[0] = *reinterpret_cast<uint32_t*>(&l01);
    lo2[1] = *reinterpret_cast<uint32_t*>(&l23);
}

// copy one packed weight matrix (hi+lo, 64KB) into padded smem
__device__ __forceinline__ void copy_B(char* sm, int mat, int nt, int tid) {
    const uint4* src = (const uint4*)(g_Wb + (size_t)((mat*2 + nt)*2) * 16384);
    #pragma unroll 4
    for (int i = tid; i < 4096; i += 256) {
        int buf = i >> 11;            // 0 = hi, 1 = lo
        int j   = i & 2047;           // uint4 within matrix
        int row = j >> 4, chunk = j & 15;
        uint4 v = src[(size_t)buf*2048 + j];
        *(uint4*)(sm + (buf ? B_LO_OFF : B_HI_OFF) + row*ROWB + chunk*16) = v;
    }
}

// warp GEMM: 16 rows x 128 cols, K=128, 3-term bf16 emulated fp32
__device__ __forceinline__ void warp_gemm(const char* sm, int w, int g, int tig,
                                          float acc[16][4]) {
    const uint32_t abase = (uint32_t)(16*w + g)*ROWB + tig*4;
    #pragma unroll
    for (int kk = 0; kk < 8; kk++) {
        uint32_t ao = abase + kk*32;
        uint32_t ah0 = *(const uint32_t*)(sm + A_HI_OFF + ao);
        uint32_t ah1 = *(const uint32_t*)(sm + A_HI_OFF + ao + 8*ROWB);
        uint32_t ah2 = *(const uint32_t*)(sm + A_HI_OFF + ao + 16);
        uint32_t ah3 = *(const uint32_t*)(sm + A_HI_OFF + ao + 8*ROWB + 16);
        uint32_t al0 = *(const uint32_t*)(sm + A_LO_OFF + ao);
        uint32_t al1 = *(const uint32_t*)(sm + A_LO_OFF + ao + 8*ROWB);
        uint32_t al2 = *(const uint32_t*)(sm + A_LO_OFF + ao + 16);
        uint32_t al3 = *(const uint32_t*)(sm + A_LO_OFF + ao + 8*ROWB + 16);
        #pragma unroll
        for (int nt = 0; nt < 16; nt++) {
            uint32_t bo = (uint32_t)(nt*8 + g)*ROWB + kk*32 + tig*4;
            uint32_t bh0 = *(const uint32_t*)(sm + B_HI_OFF + bo);
            uint32_t bh1 = *(const uint32_t*)(sm + B_HI_OFF + bo + 16);
            uint32_t bl0 = *(const uint32_t*)(sm + B_LO_OFF + bo);
            uint32_t bl1 = *(const uint32_t*)(sm + B_LO_OFF + bo + 16);
            MMA16816(acc[nt], ah0, ah1, ah2, ah3, bh0, bh1);
            MMA16816(acc[nt], al0, al1, al2, al3, bh0, bh1);
            MMA16816(acc[nt], ah0, ah1, ah2, ah3, bl0, bl1);
        }
    }
}

// ---------------- proj: Ktr, Mtr, Q via mma.sync ----------------
__global__ void __launch_bounds__(256) proj_mma_kernel(const float* __restrict__ x,
                                                       const float* __restrict__ bq) {
    extern __shared__ char sm[];
    int tid = threadIdx.x;
    int w = tid >> 5, lane = tid & 31, g = lane >> 2, tig = lane & 3;

    int blk = blockIdx.x;
    int ntp = blk >= TILES;
    int tb  = blk - ntp*TILES;
    int base = tb*128; if (base > NN-128) base = NN-128;
    size_t nbase = (size_t)ntp*NN + base;

    // stage A: x rows -> bf16 hi/lo smem
    #pragma unroll 4
    for (int j = 0; j < 16; j++) {
        int idx = tid + j*256;             // 4096 float4
        int row = idx >> 5, c4 = idx & 31;
        float4 v = ((const float4*)(x + (nbase + row)*INF))[c4];
        uint32_t hi[2], lo[2];
        split4(v, hi, lo);
        *(uint32_t*)(sm + A_HI_OFF + row*ROWB + c4*8)     = hi[0];
        *(uint32_t*)(sm + A_HI_OFF + row*ROWB + c4*8 + 4) = hi[1];
        *(uint32_t*)(sm + A_LO_OFF + row*ROWB + c4*8)     = lo[0];
        *(uint32_t*)(sm + A_LO_OFF + row*ROWB + c4*8 + 4) = lo[1];
    }

    for (int m = 0; m < 3; m++) {
        __syncthreads();
        copy_B(sm, m, ntp, tid);
        __syncthreads();

        const float* bias = (m==0) ? g_bkA + ntp*OUTF
                          : (m==1) ? g_bmM + ntp*OUTF
                                   : bq    + ntp*OUTF;
        float acc[16][4];
        #pragma unroll
        for (int nt = 0; nt < 16; nt++) {
            float b0 = bias[nt*8 + 2*tig], b1 = bias[nt*8 + 2*tig + 1];
            acc[nt][0] = b0; acc[nt][1] = b1; acc[nt][2] = b0; acc[nt][3] = b1;
        }
        warp_gemm(sm, w, g, tig, acc);

        // epilogue: scattered float2 stores (sector-complete per quad)
        int row = 16*w + g;
        size_t nrow = nbase + row;
        float* outp; int rstride;
        if (m == 2) { outp = g_Q + nrow*OUTF; rstride = 8*OUTF; }
        else        { outp = g_KM + (nrow*2 + m)*OUTF; rstride = 8*2*OUTF; }
        #pragma unroll
        for (int nt = 0; nt < 16; nt++) {
            int col = nt*8 + 2*tig;
            *(float2*)(outp + col)           = make_float2(acc[nt][0], acc[nt][1]);
            *(float2*)(outp + rstride + col) = make_float2(acc[nt][2], acc[nt][3]);
        }
    }
}

// ---------------- edge pass (unchanged; at DRAM roofline) ----------------
__global__ void __launch_bounds__(256) edge_kernel(const int* __restrict__ ei) {
    int warp = (blockIdx.x*blockDim.x + threadIdx.x) >> 5;
    int lane = threadIdx.x & 31;
    if (warp >= 2*EE) return;
    int t = (warp >= EE);
    int e = warp - t*EE;
    int src = ei[(size_t)t*2*EE + e];
    int dst = ei[(size_t)t*2*EE + EE + e];
    int s = t, d = 1 - t;

    const float4* kq = (const float4*)(g_KM + ((size_t)(s*NN + src)*2)*OUTF);
    const float4* qp = (const float4*)(g_Q  +  (size_t)(d*NN + dst)*OUTF);
    float4 k4 = kq[lane];
    float4 q4 = qp[lane];
    float p = k4.x*q4.x + k4.y*q4.y + k4.z*q4.z + k4.w*q4.w;
    p += __shfl_down_sync(0xffffffffu, p, 4, 8);
    p += __shfl_down_sync(0xffffffffu, p, 2, 8);
    p += __shfl_down_sync(0xffffffffu, p, 1, 8);
    float att = __shfl_sync(0xffffffffu, p, 0, 8);
    float ev  = __expf(att);

    const float4* mp = (const float4*)(g_KM + ((size_t)(s*NN + src)*2 + 1)*OUTF);
    float4 m4 = mp[lane];

    float* arow = g_agg + (size_t)(d*NN + dst)*OUTF + lane*4;
    asm volatile("red.global.add.v4.f32 [%0], {%1,%2,%3,%4};"
                 :: "l"(arow), "f"(m4.x*ev), "f"(m4.y*ev), "f"(m4.z*ev), "f"(m4.w*ev)
                 : "memory");
    if ((lane & 7) == 0)
        atomicAdd(g_den + (size_t)(d*NN + dst)*HH + (lane >> 3), ev);
}

// ---------------- node pass: gelu(agg/den) -> mma GEMM -> skip + LN ----------------
__global__ void __launch_bounds__(256) node_mma_kernel(const float* __restrict__ x,
                                                       const float* __restrict__ ba,
                                                       const float* __restrict__ skip,
                                                       const float* __restrict__ lns,
                                                       const float* __restrict__ lnb,
                                                       float* __restrict__ out) {
    extern __shared__ char sm[];
    float* S = (float*)sm;                    // reuse A region: [128][136] f32 = 69632B
    int tid = threadIdx.x;
    int w = tid >> 5, lane = tid & 31, g = lane >> 2, tig = lane & 3;

    int blk = blockIdx.x;
    int ntp = blk >= TILES;
    int tb  = blk - ntp*TILES;
    int base = tb*128; if (base > NN-128) base = NN-128;
    size_t nbase = (size_t)ntp*NN + base;

    // stage A = gelu(agg/den) -> bf16 hi/lo smem
    #pragma unroll 4
    for (int j = 0; j < 16; j++) {
        int idx = tid + j*256;
        int row = idx >> 5, c4 = idx & 31;
        size_t nrow = nbase + row;
        float4 v = ((const float4*)(g_agg + nrow*OUTF))[c4];
        float idn = 1.f / (g_den[nrow*HH + (c4 >> 3)] + 1e-16f);
        v.x *= idn; v.y *= idn; v.z *= idn; v.w *= idn;
        v.x = 0.5f*v.x*(1.f + erff(v.x*0.70710678118654752f));
        v.y = 0.5f*v.y*(1.f + erff(v.y*0.70710678118654752f));
        v.z = 0.5f*v.z*(1.f + erff(v.z*0.70710678118654752f));
        v.w = 0.5f*v.w*(1.f + erff(v.w*0.70710678118654752f));
        uint32_t hi[2], lo[2];
        split4(v, hi, lo);
        *(uint32_t*)(sm + A_HI_OFF + row*ROWB + c4*8)     = hi[0];
        *(uint32_t*)(sm + A_HI_OFF + row*ROWB + c4*8 + 4) = hi[1];
        *(uint32_t*)(sm + A_LO_OFF + row*ROWB + c4*8)     = lo[0];
        *(uint32_t*)(sm + A_LO_OFF + row*ROWB + c4*8 + 4) = lo[1];
    }
    __syncthreads();
    copy_B(sm, 3, ntp, tid);
    __syncthreads();

    float acc[16][4];
    #pragma unroll
    for (int nt = 0; nt < 16; nt++) {
        float b0 = ba[ntp*OUTF + nt*8 + 2*tig], b1 = ba[ntp*OUTF + nt*8 + 2*tig + 1];
        acc[nt][0] = b0; acc[nt][1] = b1; acc[nt][2] = b0; acc[nt][3] = b1;
    }
    warp_gemm(sm, w, g, tig, acc);
    __syncthreads();   // all warps done reading A region before reuse as S

    // acc -> S [128][136] f32
    {
        int row = 16*w + g;
        #pragma unroll
        for (int nt = 0; nt < 16; nt++) {
            int col = nt*8 + 2*tig;
            S[row*136 + col]     = acc[nt][0];
            S[row*136 + col + 1] = acc[nt][1];
            S[(row+8)*136 + col]     = acc[nt][2];
            S[(row+8)*136 + col + 1] = acc[nt][3];
        }
    }
    __syncthreads();

    // skip blend
    float alpha = 1.f / (1.f + __expf(-skip[ntp]));
    float beta  = 1.f - alpha;
    #pragma unroll 4
    for (int i = tid; i < 128*128; i += 256) {
        int r = i >> 7, c = i & 127;
        S[r*136 + c] = alpha*S[r*136 + c] + beta*x[(nbase + r)*INF + c];
    }
    __syncthreads();

    // layernorm: warp w rows 16w..16w+15
    for (int rr = 0; rr < 16; rr++) {
        int r = w*16 + rr;
        float s1 = 0.f, s2 = 0.f;
        #pragma unroll
        for (int c = lane; c < OUTF; c += 32) { float v = S[r*136 + c]; s1 += v; s2 += v*v; }
        #pragma unroll
        for (int off = 16; off; off >>= 1) {
            s1 += __shfl_xor_sync(0xffffffffu, s1, off);
            s2 += __shfl_xor_sync(0xffffffffu, s2, off);
        }
        float mean = s1 * (1.f/OUTF);
        float var  = s2 * (1.f/OUTF) - mean*mean;
        float inv  = rsqrtf(var + 1e-5f);
        #pragma unroll
        for (int c = lane; c < OUTF; c += 32)
            out[(nbase + r)*OUTF + c] = (S[r*136 + c] - mean)*inv*lns[ntp*OUTF + c]
                                        + lnb[ntp*OUTF + c];
    }
}

// ---------------- launch ----------------
extern "C" void kernel_launch(void* const* d_in, const int* in_sizes, int n_in,
                              void* d_out, int out_size) {
    const float* x     = (const float*)d_in[0];
    const int*   ei    = (const int*)  d_in[1];
    const float* Wk    = (const float*)d_in[2];
    const float* bk    = (const float*)d_in[3];
    const float* Wq    = (const float*)d_in[4];
    const float* bq    = (const float*)d_in[5];
    const float* Wm    = (const float*)d_in[6];
    const float* bm    = (const float*)d_in[7];
    const float* Wa    = (const float*)d_in[8];
    const float* ba    = (const float*)d_in[9];
    const float* w_att = (const float*)d_in[10];
    const float* w_msg = (const float*)d_in[11];
    const float* mu    = (const float*)d_in[12];
    const float* skip  = (const float*)d_in[13];
    const float* lns   = (const float*)d_in[14];
    const float* lnb   = (const float*)d_in[15];
    float* out = (float*)d_out;

    cudaFuncSetAttribute(proj_mma_kernel, cudaFuncAttributeMaxDynamicSharedMemorySize, SMEM_TOT);
    cudaFuncSetAttribute(node_mma_kernel, cudaFuncAttributeMaxDynamicSharedMemorySize, SMEM_TOT);

    prep_fold<<<256, 256>>>(Wk, bk, Wm, bm, w_att, w_msg, mu);
    prep_pack<<<512, 256>>>(Wq, Wa);
    zero_kernel<<<50000, 256>>>();
    proj_mma_kernel<<<2*TILES, 256, SMEM_TOT>>>(x, bq);
    edge_kernel<<<(2*EE*32)/256, 256>>>(ei);
    node_mma_kernel<<<2*TILES, 256, SMEM_TOT>>>(x, ba, skip, lns, lnb, out);
}

// round 4
// speedup vs baseline: 2.4027x; 1.1600x over previous
#include <cuda_runtime.h>
#include <cuda_bf16.h>
#include <cuda_fp16.h>
#include <math.h>
#include <stdint.h>

#define NN 200000
#define EE 1000000
#define INF 128
#define OUTF 128
#define HH 4
#define DKK 32
#define TILES 1563            // ceil(NN/128)

// smem layout (bytes): rows padded to 272B (conflict-free LDSM: 8 rows hit 8 distinct 4-bank groups)
#define ROWB 272
#define A_HI_OFF 0
#define A_LO_OFF 34816
#define B_HI_OFF 69632
#define B_LO_OFF 104448
#define SMEM_TOT 139264

// ---------------- scratch (device globals; no allocation) ----------------
__device__ __half g_KMh[(size_t)2*NN*2*OUTF];   // K/M interleaved fp16: [2N][2][128]
__device__ __half g_Qh [(size_t)2*NN*OUTF];     // fp16
__device__ float  g_agg[(size_t)2*NN*OUTF];
__device__ float  g_den[(size_t)2*NN*HH];
__device__ float  g_WkA[2*INF*OUTF];
__device__ float  g_bkA[2*OUTF];
__device__ float  g_WmM[2*INF*OUTF];
__device__ float  g_bmM[2*OUTF];
// packed bf16 hi/lo weights, W^T layout [o][k]: [mat(4)][type(2)][hl(2)][128*128]
__device__ __nv_bfloat16 g_Wb[(size_t)4*2*2*16384];

#define MMA16816(acc, A0,A1,A2,A3, B0,B1) \
  asm volatile("mma.sync.aligned.m16n8k16.row.col.f32.bf16.bf16.f32 " \
    "{%0,%1,%2,%3}, {%4,%5,%6,%7}, {%8,%9}, {%0,%1,%2,%3};" \
    : "+f"((acc)[0]), "+f"((acc)[1]), "+f"((acc)[2]), "+f"((acc)[3]) \
    : "r"(A0), "r"(A1), "r"(A2), "r"(A3), "r"(B0), "r"(B1))

#define LDSM4(r0,r1,r2,r3,addr) \
  asm volatile("ldmatrix.sync.aligned.m8n8.x4.shared.b16 {%0,%1,%2,%3}, [%4];" \
    : "=r"(r0), "=r"(r1), "=r"(r2), "=r"(r3) : "r"(addr))

__device__ __forceinline__ uint32_t smem_u32(const void* p) {
    uint32_t a;
    asm("{ .reg .u64 t; cvta.to.shared.u64 t, %1; cvt.u32.u64 %0, t; }" : "=r"(a) : "l"(p));
    return a;
}

// ---------------- prep: fold w_att/w_msg (+ mu*scale) into projection weights
__global__ void prep_fold(const float* __restrict__ Wk, const float* __restrict__ bk,
                          const float* __restrict__ Wm, const float* __restrict__ bm,
                          const float* __restrict__ w_att, const float* __restrict__ w_msg,
                          const float* __restrict__ mu) {
    int idx = blockIdx.x*blockDim.x + threadIdx.x;     // 65536
    const int total = 2*INF*OUTF;
    int m   = idx / total;
    int rem = idx - m*total;
    int t   = rem / (INF*OUTF);
    int io  = rem - t*(INF*OUTF);
    int i   = io / OUTF;
    int o   = io - i*OUTF;
    int h   = o >> 5, f = o & 31;

    const float* W = m ? Wm : Wk;
    const float* R = m ? w_msg : w_att;
    const float* wrow = W + ((size_t)t*INF + i)*OUTF + h*DKK;
    const float* rr   = R + (((size_t)t*HH + h)*DKK)*DKK + f;
    float s = 0.f;
    #pragma unroll
    for (int d = 0; d < DKK; d++) s += wrow[d] * rr[(size_t)d*DKK];
    float fold = m ? 1.f : mu[t*HH + h] * 0.17677669529663687f;   // mu / sqrt(DK)
    (m ? g_WmM : g_WkA)[(size_t)t*INF*OUTF + io] = s * fold;

    if (i == 0) {
        const float* b = m ? bm : bk;
        float sb = 0.f;
        #pragma unroll
        for (int d = 0; d < DKK; d++) sb += b[t*OUTF + h*DKK + d] * rr[(size_t)d*DKK];
        (m ? g_bmM : g_bkA)[t*OUTF + o] = sb * fold;
    }
}

// pack 4 matrices (Kfold, Mfold, Q, A) per type as W^T [o][k] bf16 hi/lo
__global__ void prep_pack(const float* __restrict__ Wq, const float* __restrict__ Wa) {
    int idx = blockIdx.x*blockDim.x + threadIdx.x;   // 131072
    int mat = idx >> 15;
    int rem = idx & 32767;
    int t   = rem >> 14;
    int ok  = rem & 16383;
    int o   = ok >> 7;
    int k   = ok & 127;
    const float* W = (mat==0) ? g_WkA : (mat==1) ? g_WmM : (mat==2) ? Wq : Wa;
    float v = W[((size_t)t*INF + k)*OUTF + o];
    __nv_bfloat16 h = __float2bfloat16(v);
    __nv_bfloat16 l = __float2bfloat16(v - __bfloat162float(h));
    size_t b = (size_t)((mat*2 + t)*2) * 16384;
    g_Wb[b + ok]         = h;
    g_Wb[b + 16384 + ok] = l;
}

// ---------------- zero agg + den ----------------
__global__ void zero_kernel() {
    size_t i = (size_t)blockIdx.x*blockDim.x + threadIdx.x;
    const size_t n4 = (size_t)2*NN*OUTF/4;
    if (i < n4) ((float4*)g_agg)[i] = make_float4(0.f,0.f,0.f,0.f);
    if (i < (size_t)2*NN*HH) g_den[i] = 0.f;
}

// split float4 -> two bf16x2 hi words + two lo words
__device__ __forceinline__ void split4(float4 v, uint32_t* hi2, uint32_t* lo2) {
    __nv_bfloat162 h01 = __floats2bfloat162_rn(v.x, v.y);
    __nv_bfloat162 h23 = __floats2bfloat162_rn(v.z, v.w);
    __nv_bfloat162 l01 = __floats2bfloat162_rn(v.x - __bfloat162float(h01.x),
                                               v.y - __bfloat162float(h01.y));
    __nv_bfloat162 l23 = __floats2bfloat162_rn(v.z - __bfloat162float(h23.x),
                                               v.w - __bfloat162float(h23.y));
    hi2[0] = *reinterpret_cast<uint32_t*>(&h01);
    hi2[1] = *reinterpret_cast<uint32_t*>(&h23);
    lo2[0] = *reinterpret_cast<uint32_t*>(&l01);
    lo2[1] = *reinterpret_cast<uint32_t*>(&l23);
}

// copy one packed weight matrix (hi+lo, 64KB) into padded smem
__device__ __forceinline__ void copy_B(char* sm, int mat, int nt, int tid) {
    const uint4* src = (const uint4*)(g_Wb + (size_t)((mat*2 + nt)*2) * 16384);
    #pragma unroll 4
    for (int i = tid; i < 4096; i += 256) {
        int buf = i >> 11;            // 0 = hi, 1 = lo
        int j   = i & 2047;
        int row = j >> 4, chunk = j & 15;
        uint4 v = src[(size_t)buf*2048 + j];
        *(uint4*)(sm + (buf ? B_LO_OFF : B_HI_OFF) + row*ROWB + chunk*16) = v;
    }
}

// warp GEMM: 32 rows x 64 cols per warp (8 warps: wm = w&3, wn = w>>2), K=128,
// 3-term bf16 emulated fp32, ldmatrix fragment loads, B cached in regs per k-step
__device__ __forceinline__ void warp_gemm(uint32_t su, int w, int lane,
                                          float acc[2][8][4]) {
    int wm = w & 3, wn = w >> 2;
    int mat = lane >> 3, r8 = lane & 7;
    // A x4 order: [r0-7,k0-7],[r8-15,k0-7],[r0-7,k8-15],[r8-15,k8-15]
    uint32_t aoff = (uint32_t)(wm*32 + (mat&1)*8 + r8)*ROWB + (mat>>1)*16;
    // B x4 order: [n0-7,k0-7],[n0-7,k8-15],[n8-15,k0-7],[n8-15,k8-15]
    uint32_t boff = (uint32_t)(wn*64 + (mat>>1)*8 + r8)*ROWB + (mat&1)*16;

    #pragma unroll
    for (int kk = 0; kk < 8; kk++) {
        uint32_t kb = kk*32;
        uint32_t Ah[2][4], Al[2][4], Bh[8][2], Bl[8][2];
        #pragma unroll
        for (int mt = 0; mt < 2; mt++) {
            uint32_t ao = aoff + mt*16*ROWB + kb;
            LDSM4(Ah[mt][0], Ah[mt][1], Ah[mt][2], Ah[mt][3], su + A_HI_OFF + ao);
            LDSM4(Al[mt][0], Al[mt][1], Al[mt][2], Al[mt][3], su + A_LO_OFF + ao);
        }
        #pragma unroll
        for (int p = 0; p < 4; p++) {
            uint32_t bo = boff + p*16*ROWB + kb;
            LDSM4(Bh[2*p][0], Bh[2*p][1], Bh[2*p+1][0], Bh[2*p+1][1], su + B_HI_OFF + bo);
            LDSM4(Bl[2*p][0], Bl[2*p][1], Bl[2*p+1][0], Bl[2*p+1][1], su + B_LO_OFF + bo);
        }
        #pragma unroll
        for (int mt = 0; mt < 2; mt++)
            #pragma unroll
            for (int nt = 0; nt < 8; nt++) {
                MMA16816(acc[mt][nt], Ah[mt][0],Ah[mt][1],Ah[mt][2],Ah[mt][3], Bh[nt][0],Bh[nt][1]);
                MMA16816(acc[mt][nt], Al[mt][0],Al[mt][1],Al[mt][2],Al[mt][3], Bh[nt][0],Bh[nt][1]);
                MMA16816(acc[mt][nt], Ah[mt][0],Ah[mt][1],Ah[mt][2],Ah[mt][3], Bl[nt][0],Bl[nt][1]);
            }
    }
}

// ---------------- proj: Ktr, Mtr, Q via mma.sync -> fp16 tables ----------------
__global__ void __launch_bounds__(256) proj_mma_kernel(const float* __restrict__ x,
                                                       const float* __restrict__ bq) {
    extern __shared__ char sm[];
    uint32_t su = smem_u32(sm);
    int tid = threadIdx.x;
    int w = tid >> 5, lane = tid & 31;
    int wm = w & 3, wn = w >> 2;

    int blk = blockIdx.x;
    int ntp = blk >= TILES;
    int tb  = blk - ntp*TILES;
    int base = tb*128; if (base > NN-128) base = NN-128;
    size_t nbase = (size_t)ntp*NN + base;

    // stage A: x rows -> bf16 hi/lo smem
    #pragma unroll 4
    for (int j = 0; j < 16; j++) {
        int idx = tid + j*256;             // 4096 float4
        int row = idx >> 5, c4 = idx & 31;
        float4 v = ((const float4*)(x + (nbase + row)*INF))[c4];
        uint32_t hi[2], lo[2];
        split4(v, hi, lo);
        *(uint32_t*)(sm + A_HI_OFF + row*ROWB + c4*8)     = hi[0];
        *(uint32_t*)(sm + A_HI_OFF + row*ROWB + c4*8 + 4) = hi[1];
        *(uint32_t*)(sm + A_LO_OFF + row*ROWB + c4*8)     = lo[0];
        *(uint32_t*)(sm + A_LO_OFF + row*ROWB + c4*8 + 4) = lo[1];
    }

    for (int m = 0; m < 3; m++) {
        __syncthreads();
        copy_B(sm, m, ntp, tid);
        __syncthreads();

        const float* bias = (m==0) ? g_bkA + ntp*OUTF
                          : (m==1) ? g_bmM + ntp*OUTF
                                   : bq    + ntp*OUTF;
        float acc[2][8][4];
        #pragma unroll
        for (int mt = 0; mt < 2; mt++)
            #pragma unroll
            for (int nt = 0; nt < 8; nt++) {
                int col = wn*64 + nt*8 + 2*(lane & 3);
                float b0 = bias[col], b1 = bias[col+1];
                acc[mt][nt][0] = b0; acc[mt][nt][1] = b1;
                acc[mt][nt][2] = b0; acc[mt][nt][3] = b1;
            }
        warp_gemm(su, w, lane, acc);
        __syncthreads();   // all warps done reading B before staging reuses it

        // stage fp16 result into B_HI region: [128] rows x ROWB stride
        __half* H = (__half*)(sm + B_HI_OFF);
        #pragma unroll
        for (int mt = 0; mt < 2; mt++)
            #pragma unroll
            for (int nt = 0; nt < 8; nt++) {
                int row = wm*32 + mt*16 + (lane >> 2);
                int col = wn*64 + nt*8 + 2*(lane & 3);
                *(__half2*)((char*)H + row*ROWB + col*2) =
                    __floats2half2_rn(acc[mt][nt][0], acc[mt][nt][1]);
                *(__half2*)((char*)H + (row+8)*ROWB + col*2) =
                    __floats2half2_rn(acc[mt][nt][2], acc[mt][nt][3]);
            }
        __syncthreads();

        // coalesced copy-out: 128 rows x 256B
        #pragma unroll
        for (int i = tid; i < 2048; i += 256) {
            int row = i >> 4, ch = i & 15;
            uint4 v = *(uint4*)((char*)H + row*ROWB + ch*16);
            __half* dst = (m == 2) ? g_Qh + (nbase + row)*OUTF + ch*8
                                   : g_KMh + ((nbase + row)*2 + m)*OUTF + ch*8;
            *(uint4*)dst = v;
        }
    }
}

// ---------------- edge pass: fp16 gathers, f32 math + atomics ----------------
__global__ void __launch_bounds__(256) edge_kernel(const int* __restrict__ ei) {
    int warp = (blockIdx.x*blockDim.x + threadIdx.x) >> 5;
    int lane = threadIdx.x & 31;
    if (warp >= 2*EE) return;
    int t = (warp >= EE);
    int e = warp - t*EE;
    int src = ei[(size_t)t*2*EE + e];
    int dst = ei[(size_t)t*2*EE + EE + e];
    int s = t, d = 1 - t;

    const uint2* kmrow = (const uint2*)(g_KMh + (size_t)(s*NN + src)*2*OUTF);
    const uint2* qrow  = (const uint2*)(g_Qh  + (size_t)(d*NN + dst)*OUTF);
    uint2 kv = kmrow[lane];        // k[4*lane .. 4*lane+3]
    uint2 mv = kmrow[32 + lane];   // m[...]
    uint2 qv = qrow[lane];

    float2 ka = __half22float2(*(const __half2*)&kv.x);
    float2 kb = __half22float2(*(const __half2*)&kv.y);
    float2 qa = __half22float2(*(const __half2*)&qv.x);
    float2 qb = __half22float2(*(const __half2*)&qv.y);
    float p = ka.x*qa.x + ka.y*qa.y + kb.x*qb.x + kb.y*qb.y;
    p += __shfl_down_sync(0xffffffffu, p, 4, 8);
    p += __shfl_down_sync(0xffffffffu, p, 2, 8);
    p += __shfl_down_sync(0xffffffffu, p, 1, 8);
    float att = __shfl_sync(0xffffffffu, p, 0, 8);
    float ev  = __expf(att);

    float2 ma = __half22float2(*(const __half2*)&mv.x);
    float2 mb = __half22float2(*(const __half2*)&mv.y);

    float* arow = g_agg + (size_t)(d*NN + dst)*OUTF + lane*4;
    asm volatile("red.global.add.v4.f32 [%0], {%1,%2,%3,%4};"
                 :: "l"(arow), "f"(ma.x*ev), "f"(ma.y*ev), "f"(mb.x*ev), "f"(mb.y*ev)
                 : "memory");
    if ((lane & 7) == 0)
        atomicAdd(g_den + (size_t)(d*NN + dst)*HH + (lane >> 3), ev);
}

// ---------------- node pass: gelu(agg/den) -> mma GEMM -> skip + LN ----------------
__global__ void __launch_bounds__(256) node_mma_kernel(const float* __restrict__ x,
                                                       const float* __restrict__ ba,
                                                       const float* __restrict__ skip,
                                                       const float* __restrict__ lns,
                                                       const float* __restrict__ lnb,
                                                       float* __restrict__ out) {
    extern __shared__ char sm[];
    uint32_t su = smem_u32(sm);
    float* S = (float*)sm;        // reuse A region after GEMM: [128][136] f32 = 69632B
    int tid = threadIdx.x;
    int w = tid >> 5, lane = tid & 31;
    int wm = w & 3, wn = w >> 2;

    int blk = blockIdx.x;
    int ntp = blk >= TILES;
    int tb  = blk - ntp*TILES;
    int base = tb*128; if (base > NN-128) base = NN-128;
    size_t nbase = (size_t)ntp*NN + base;

    // stage A = gelu(agg/den) -> bf16 hi/lo smem
    #pragma unroll 4
    for (int j = 0; j < 16; j++) {
        int idx = tid + j*256;
        int row = idx >> 5, c4 = idx & 31;
        size_t nrow = nbase + row;
        float4 v = ((const float4*)(g_agg + nrow*OUTF))[c4];
        float idn = 1.f / (g_den[nrow*HH + (c4 >> 3)] + 1e-16f);
        v.x *= idn; v.y *= idn; v.z *= idn; v.w *= idn;
        v.x = 0.5f*v.x*(1.f + erff(v.x*0.70710678118654752f));
        v.y = 0.5f*v.y*(1.f + erff(v.y*0.70710678118654752f));
        v.z = 0.5f*v.z*(1.f + erff(v.z*0.70710678118654752f));
        v.w = 0.5f*v.w*(1.f + erff(v.w*0.70710678118654752f));
        uint32_t hi[2], lo[2];
        split4(v, hi, lo);
        *(uint32_t*)(sm + A_HI_OFF + row*ROWB + c4*8)     = hi[0];
        *(uint32_t*)(sm + A_HI_OFF + row*ROWB + c4*8 + 4) = hi[1];
        *(uint32_t*)(sm + A_LO_OFF + row*ROWB + c4*8)     = lo[0];
        *(uint32_t*)(sm + A_LO_OFF + row*ROWB + c4*8 + 4) = lo[1];
    }
    __syncthreads();
    copy_B(sm, 3, ntp, tid);
    __syncthreads();

    float acc[2][8][4];
    #pragma unroll
    for (int mt = 0; mt < 2; mt++)
        #pragma unroll
        for (int nt = 0; nt < 8; nt++) {
            int col = wn*64 + nt*8 + 2*(lane & 3);
            float b0 = ba[ntp*OUTF + col], b1 = ba[ntp*OUTF + col + 1];
            acc[mt][nt][0] = b0; acc[mt][nt][1] = b1;
            acc[mt][nt][2] = b0; acc[mt][nt][3] = b1;
        }
    warp_gemm(su, w, lane, acc);
    __syncthreads();   // all warps done reading A region before reuse as S

    // acc -> S [128][136] f32
    #pragma unroll
    for (int mt = 0; mt < 2; mt++)
        #pragma unroll
        for (int nt = 0; nt < 8; nt++) {
            int row = wm*32 + mt*16 + (lane >> 2);
            int col = wn*64 + nt*8 + 2*(lane & 3);
            *(float2*)(S + row*136 + col)     = make_float2(acc[mt][nt][0], acc[mt][nt][1]);
            *(float2*)(S + (row+8)*136 + col) = make_float2(acc[mt][nt][2], acc[mt][nt][3]);
        }
    __syncthreads();

    // skip blend
    float alpha = 1.f / (1.f + __expf(-skip[ntp]));
    float beta  = 1.f - alpha;
    #pragma unroll 4
    for (int i = tid; i < 128*128; i += 256) {
        int r = i >> 7, c = i & 127;
        S[r*136 + c] = alpha*S[r*136 + c] + beta*x[(nbase + r)*INF + c];
    }
    __syncthreads();

    // layernorm: warp w rows 16w..16w+15
    for (int rr = 0; rr < 16; rr++) {
        int r = w*16 + rr;
        float s1 = 0.f, s2 = 0.f;
        #pragma unroll
        for (int c = lane; c < OUTF; c += 32) { float v = S[r*136 + c]; s1 += v; s2 += v*v; }
        #pragma unroll
        for (int off = 16; off; off >>= 1) {
            s1 += __shfl_xor_sync(0xffffffffu, s1, off);
            s2 += __shfl_xor_sync(0xffffffffu, s2, off);
        }
        float mean = s1 * (1.f/OUTF);
        float var  = s2 * (1.f/OUTF) - mean*mean;
        float inv  = rsqrtf(var + 1e-5f);
        #pragma unroll
        for (int c = lane; c < OUTF; c += 32)
            out[(nbase + r)*OUTF + c] = (S[r*136 + c] - mean)*inv*lns[ntp*OUTF + c]
                                        + lnb[ntp*OUTF + c];
    }
}

// ---------------- launch ----------------
extern "C" void kernel_launch(void* const* d_in, const int* in_sizes, int n_in,
                              void* d_out, int out_size) {
    const float* x     = (const float*)d_in[0];
    const int*   ei    = (const int*)  d_in[1];
    const float* Wk    = (const float*)d_in[2];
    const float* bk    = (const float*)d_in[3];
    const float* Wq    = (const float*)d_in[4];
    const float* bq    = (const float*)d_in[5];
    const float* Wm    = (const float*)d_in[6];
    const float* bm    = (const float*)d_in[7];
    const float* Wa    = (const float*)d_in[8];
    const float* ba    = (const float*)d_in[9];
    const float* w_att = (const float*)d_in[10];
    const float* w_msg = (const float*)d_in[11];
    const float* mu    = (const float*)d_in[12];
    const float* skip  = (const float*)d_in[13];
    const float* lns   = (const float*)d_in[14];
    const float* lnb   = (const float*)d_in[15];
    float* out = (float*)d_out;

    cudaFuncSetAttribute(proj_mma_kernel, cudaFuncAttributeMaxDynamicSharedMemorySize, SMEM_TOT);
    cudaFuncSetAttribute(node_mma_kernel, cudaFuncAttributeMaxDynamicSharedMemorySize, SMEM_TOT);

    prep_fold<<<256, 256>>>(Wk, bk, Wm, bm, w_att, w_msg, mu);
    prep_pack<<<512, 256>>>(Wq, Wa);
    zero_kernel<<<50000, 256>>>();
    proj_mma_kernel<<<2*TILES, 256, SMEM_TOT>>>(x, bq);
    edge_kernel<<<(2*EE*32)/256, 256>>>(ei);
    node_mma_kernel<<<2*TILES, 256, SMEM_TOT>>>(x, ba, skip, lns, lnb, out);
}

// round 5
// speedup vs baseline: 3.1199x; 1.2985x over previous
#include <cuda_runtime.h>
#include <cuda_bf16.h>
#include <cuda_fp16.h>
#include <math.h>
#include <stdint.h>

#define NN 200000
#define EE 1000000
#define INF 128
#define OUTF 128
#define HH 4
#define DKK 32
#define TILES 1563            // ceil(NN/128)

// smem layout (bytes): rows padded to 272B (conflict-free LDSM)
#define ROWB 272
#define A_HI_OFF 0
#define A_LO_OFF 34816
#define B_OFF    69632        // single 34816B buffer, hi then lo streamed through
#define SMEM_TOT 104448       // 2 CTAs/SM (208896 <= 228KB)

// ---------------- scratch (device globals; no allocation) ----------------
__device__ __half g_KMh[(size_t)2*NN*2*OUTF];   // K/M interleaved fp16: [2N][2][128]
__device__ __half g_Qh [(size_t)2*NN*OUTF];     // fp16
__device__ float  g_agg[(size_t)2*NN*OUTF];
__device__ float  g_den[(size_t)2*NN*HH];
__device__ float  g_WkA[2*INF*OUTF];
__device__ float  g_bkA[2*OUTF];
__device__ float  g_WmM[2*INF*OUTF];
__device__ float  g_bmM[2*OUTF];
// packed bf16 hi/lo weights, W^T layout [o][k]: [mat(4)][type(2)][hl(2)][128*128]
__device__ __nv_bfloat16 g_Wb[(size_t)4*2*2*16384];

#define MMA16816(acc, A0,A1,A2,A3, B0,B1) \
  asm volatile("mma.sync.aligned.m16n8k16.row.col.f32.bf16.bf16.f32 " \
    "{%0,%1,%2,%3}, {%4,%5,%6,%7}, {%8,%9}, {%0,%1,%2,%3};" \
    : "+f"((acc)[0]), "+f"((acc)[1]), "+f"((acc)[2]), "+f"((acc)[3]) \
    : "r"(A0), "r"(A1), "r"(A2), "r"(A3), "r"(B0), "r"(B1))

#define LDSM4(r0,r1,r2,r3,addr) \
  asm volatile("ldmatrix.sync.aligned.m8n8.x4.shared.b16 {%0,%1,%2,%3}, [%4];" \
    : "=r"(r0), "=r"(r1), "=r"(r2), "=r"(r3) : "r"(addr))

__device__ __forceinline__ uint32_t smem_u32(const void* p) {
    uint32_t a;
    asm("{ .reg .u64 t; cvta.to.shared.u64 t, %1; cvt.u32.u64 %0, t; }" : "=r"(a) : "l"(p));
    return a;
}

// ---------------- prep: fold w_att/w_msg (+ mu*scale) into projection weights
__global__ void prep_fold(const float* __restrict__ Wk, const float* __restrict__ bk,
                          const float* __restrict__ Wm, const float* __restrict__ bm,
                          const float* __restrict__ w_att, const float* __restrict__ w_msg,
                          const float* __restrict__ mu) {
    int idx = blockIdx.x*blockDim.x + threadIdx.x;     // 65536
    const int total = 2*INF*OUTF;
    int m   = idx / total;
    int rem = idx - m*total;
    int t   = rem / (INF*OUTF);
    int io  = rem - t*(INF*OUTF);
    int i   = io / OUTF;
    int o   = io - i*OUTF;
    int h   = o >> 5, f = o & 31;

    const float* W = m ? Wm : Wk;
    const float* R = m ? w_msg : w_att;
    const float* wrow = W + ((size_t)t*INF + i)*OUTF + h*DKK;
    const float* rr   = R + (((size_t)t*HH + h)*DKK)*DKK + f;
    float s = 0.f;
    #pragma unroll
    for (int d = 0; d < DKK; d++) s += wrow[d] * rr[(size_t)d*DKK];
    float fold = m ? 1.f : mu[t*HH + h] * 0.17677669529663687f;   // mu / sqrt(DK)
    (m ? g_WmM : g_WkA)[(size_t)t*INF*OUTF + io] = s * fold;

    if (i == 0) {
        const float* b = m ? bm : bk;
        float sb = 0.f;
        #pragma unroll
        for (int d = 0; d < DKK; d++) sb += b[t*OUTF + h*DKK + d] * rr[(size_t)d*DKK];
        (m ? g_bmM : g_bkA)[t*OUTF + o] = sb * fold;
    }
}

// pack 4 matrices (Kfold, Mfold, Q, A) per type as W^T [o][k] bf16 hi/lo
__global__ void prep_pack(const float* __restrict__ Wq, const float* __restrict__ Wa) {
    int idx = blockIdx.x*blockDim.x + threadIdx.x;   // 131072
    int mat = idx >> 15;
    int rem = idx & 32767;
    int t   = rem >> 14;
    int ok  = rem & 16383;
    int o   = ok >> 7;
    int k   = ok & 127;
    const float* W = (mat==0) ? g_WkA : (mat==1) ? g_WmM : (mat==2) ? Wq : Wa;
    float v = W[((size_t)t*INF + k)*OUTF + o];
    __nv_bfloat16 h = __float2bfloat16(v);
    __nv_bfloat16 l = __float2bfloat16(v - __bfloat162float(h));
    size_t b = (size_t)((mat*2 + t)*2) * 16384;
    g_Wb[b + ok]         = h;
    g_Wb[b + 16384 + ok] = l;
}

// ---------------- zero agg + den ----------------
__global__ void zero_kernel() {
    size_t i = (size_t)blockIdx.x*blockDim.x + threadIdx.x;
    const size_t n4 = (size_t)2*NN*OUTF/4;
    if (i < n4) ((float4*)g_agg)[i] = make_float4(0.f,0.f,0.f,0.f);
    if (i < (size_t)2*NN*HH) g_den[i] = 0.f;
}

// split float4 -> two bf16x2 hi words + two lo words
__device__ __forceinline__ void split4(float4 v, uint32_t* hi2, uint32_t* lo2) {
    __nv_bfloat162 h01 = __floats2bfloat162_rn(v.x, v.y);
    __nv_bfloat162 h23 = __floats2bfloat162_rn(v.z, v.w);
    __nv_bfloat162 l01 = __floats2bfloat162_rn(v.x - __bfloat162float(h01.x),
                                               v.y - __bfloat162float(h01.y));
    __nv_bfloat162 l23 = __floats2bfloat162_rn(v.z - __bfloat162float(h23.x),
                                               v.w - __bfloat162float(h23.y));
    hi2[0] = *reinterpret_cast<uint32_t*>(&h01);
    hi2[1] = *reinterpret_cast<uint32_t*>(&h23);
    lo2[0] = *reinterpret_cast<uint32_t*>(&l01);
    lo2[1] = *reinterpret_cast<uint32_t*>(&l23);
}

// copy one 32KB half (hi or lo) of a packed weight matrix into the B buffer
__device__ __forceinline__ void copy_B_half(char* sm, int mat, int nt, int half, int tid) {
    const uint4* src = (const uint4*)(g_Wb + (size_t)((mat*2 + nt)*2 + half) * 16384);
    #pragma unroll 2
    for (int i = tid; i < 2048; i += 256) {
        int row = i >> 4, chunk = i & 15;
        *(uint4*)(sm + B_OFF + row*ROWB + chunk*16) = src[i];
    }
}

// pass 1: with Bh resident, accumulate Ah*Bh + Al*Bh
__device__ __forceinline__ void gemm_pass1(uint32_t su, int w, int lane, float acc[2][8][4]) {
    int wm = w & 3, wn = w >> 2;
    int mat = lane >> 3, r8 = lane & 7;
    uint32_t aoff = (uint32_t)(wm*32 + (mat&1)*8 + r8)*ROWB + (mat>>1)*16;
    uint32_t boff = (uint32_t)(wn*64 + (mat>>1)*8 + r8)*ROWB + (mat&1)*16;

    #pragma unroll
    for (int kk = 0; kk < 8; kk++) {
        uint32_t kb = kk*32;
        uint32_t Ah[2][4], Al[2][4], B[8][2];
        #pragma unroll
        for (int mt = 0; mt < 2; mt++) {
            uint32_t ao = aoff + mt*16*ROWB + kb;
            LDSM4(Ah[mt][0], Ah[mt][1], Ah[mt][2], Ah[mt][3], su + A_HI_OFF + ao);
            LDSM4(Al[mt][0], Al[mt][1], Al[mt][2], Al[mt][3], su + A_LO_OFF + ao);
        }
        #pragma unroll
        for (int p = 0; p < 4; p++) {
            uint32_t bo = boff + p*16*ROWB + kb;
            LDSM4(B[2*p][0], B[2*p][1], B[2*p+1][0], B[2*p+1][1], su + B_OFF + bo);
        }
        #pragma unroll
        for (int mt = 0; mt < 2; mt++)
            #pragma unroll
            for (int nt = 0; nt < 8; nt++) {
                MMA16816(acc[mt][nt], Ah[mt][0],Ah[mt][1],Ah[mt][2],Ah[mt][3], B[nt][0],B[nt][1]);
                MMA16816(acc[mt][nt], Al[mt][0],Al[mt][1],Al[mt][2],Al[mt][3], B[nt][0],B[nt][1]);
            }
    }
}

// pass 2: with Bl resident, accumulate Ah*Bl
__device__ __forceinline__ void gemm_pass2(uint32_t su, int w, int lane, float acc[2][8][4]) {
    int wm = w & 3, wn = w >> 2;
    int mat = lane >> 3, r8 = lane & 7;
    uint32_t aoff = (uint32_t)(wm*32 + (mat&1)*8 + r8)*ROWB + (mat>>1)*16;
    uint32_t boff = (uint32_t)(wn*64 + (mat>>1)*8 + r8)*ROWB + (mat&1)*16;

    #pragma unroll
    for (int kk = 0; kk < 8; kk++) {
        uint32_t kb = kk*32;
        uint32_t Ah[2][4], B[8][2];
        #pragma unroll
        for (int mt = 0; mt < 2; mt++) {
            uint32_t ao = aoff + mt*16*ROWB + kb;
            LDSM4(Ah[mt][0], Ah[mt][1], Ah[mt][2], Ah[mt][3], su + A_HI_OFF + ao);
        }
        #pragma unroll
        for (int p = 0; p < 4; p++) {
            uint32_t bo = boff + p*16*ROWB + kb;
            LDSM4(B[2*p][0], B[2*p][1], B[2*p+1][0], B[2*p+1][1], su + B_OFF + bo);
        }
        #pragma unroll
        for (int mt = 0; mt < 2; mt++)
            #pragma unroll
            for (int nt = 0; nt < 8; nt++)
                MMA16816(acc[mt][nt], Ah[mt][0],Ah[mt][1],Ah[mt][2],Ah[mt][3], B[nt][0],B[nt][1]);
    }
}

// ---------------- proj: Ktr, Mtr, Q via mma.sync -> fp16 tables ----------------
__global__ void __launch_bounds__(256, 2) proj_mma_kernel(const float* __restrict__ x,
                                                          const float* __restrict__ bq) {
    extern __shared__ char sm[];
    uint32_t su = smem_u32(sm);
    int tid = threadIdx.x;
    int w = tid >> 5, lane = tid & 31;
    int wm = w & 3, wn = w >> 2;

    int blk = blockIdx.x;
    int ntp = blk >= TILES;
    int tb  = blk - ntp*TILES;
    int base = tb*128; if (base > NN-128) base = NN-128;
    size_t nbase = (size_t)ntp*NN + base;

    // stage A: x rows -> bf16 hi/lo smem
    #pragma unroll 4
    for (int j = 0; j < 16; j++) {
        int idx = tid + j*256;             // 4096 float4
        int row = idx >> 5, c4 = idx & 31;
        float4 v = ((const float4*)(x + (nbase + row)*INF))[c4];
        uint32_t hi[2], lo[2];
        split4(v, hi, lo);
        *(uint32_t*)(sm + A_HI_OFF + row*ROWB + c4*8)     = hi[0];
        *(uint32_t*)(sm + A_HI_OFF + row*ROWB + c4*8 + 4) = hi[1];
        *(uint32_t*)(sm + A_LO_OFF + row*ROWB + c4*8)     = lo[0];
        *(uint32_t*)(sm + A_LO_OFF + row*ROWB + c4*8 + 4) = lo[1];
    }

    for (int m = 0; m < 3; m++) {
        __syncthreads();
        copy_B_half(sm, m, ntp, 0, tid);   // Bh
        __syncthreads();

        const float* bias = (m==0) ? g_bkA + ntp*OUTF
                          : (m==1) ? g_bmM + ntp*OUTF
                                   : bq    + ntp*OUTF;
        float acc[2][8][4];
        #pragma unroll
        for (int mt = 0; mt < 2; mt++)
            #pragma unroll
            for (int nt = 0; nt < 8; nt++) {
                int col = wn*64 + nt*8 + 2*(lane & 3);
                float b0 = bias[col], b1 = bias[col+1];
                acc[mt][nt][0] = b0; acc[mt][nt][1] = b1;
                acc[mt][nt][2] = b0; acc[mt][nt][3] = b1;
            }
        gemm_pass1(su, w, lane, acc);
        __syncthreads();
        copy_B_half(sm, m, ntp, 1, tid);   // Bl
        __syncthreads();
        gemm_pass2(su, w, lane, acc);
        __syncthreads();   // all warps done with B buffer before fp16 staging reuses it

        // stage fp16 result into B buffer: 128 rows x 256B (+ ROWB pad)
        __half* H = (__half*)(sm + B_OFF);
        #pragma unroll
        for (int mt = 0; mt < 2; mt++)
            #pragma unroll
            for (int nt = 0; nt < 8; nt++) {
                int row = wm*32 + mt*16 + (lane >> 2);
                int col = wn*64 + nt*8 + 2*(lane & 3);
                *(__half2*)((char*)H + row*ROWB + col*2) =
                    __floats2half2_rn(acc[mt][nt][0], acc[mt][nt][1]);
                *(__half2*)((char*)H + (row+8)*ROWB + col*2) =
                    __floats2half2_rn(acc[mt][nt][2], acc[mt][nt][3]);
            }
        __syncthreads();

        // coalesced copy-out: 128 rows x 256B
        #pragma unroll
        for (int i = tid; i < 2048; i += 256) {
            int row = i >> 4, ch = i & 15;
            uint4 v = *(uint4*)((char*)H + row*ROWB + ch*16);
            __half* dst = (m == 2) ? g_Qh + (nbase + row)*OUTF + ch*8
                                   : g_KMh + ((nbase + row)*2 + m)*OUTF + ch*8;
            *(uint4*)dst = v;
        }
    }
}

// ---------------- edge pass: fp16 gathers, f32 math + atomics ----------------
__global__ void __launch_bounds__(256) edge_kernel(const int* __restrict__ ei) {
    int warp = (blockIdx.x*blockDim.x + threadIdx.x) >> 5;
    int lane = threadIdx.x & 31;
    if (warp >= 2*EE) return;
    int t = (warp >= EE);
    int e = warp - t*EE;
    int src = ei[(size_t)t*2*EE + e];
    int dst = ei[(size_t)t*2*EE + EE + e];
    int s = t, d = 1 - t;

    const uint2* kmrow = (const uint2*)(g_KMh + (size_t)(s*NN + src)*2*OUTF);
    const uint2* qrow  = (const uint2*)(g_Qh  + (size_t)(d*NN + dst)*OUTF);
    uint2 kv = kmrow[lane];
    uint2 mv = kmrow[32 + lane];
    uint2 qv = qrow[lane];

    float2 ka = __half22float2(*(const __half2*)&kv.x);
    float2 kb = __half22float2(*(const __half2*)&kv.y);
    float2 qa = __half22float2(*(const __half2*)&qv.x);
    float2 qb = __half22float2(*(const __half2*)&qv.y);
    float p = ka.x*qa.x + ka.y*qa.y + kb.x*qb.x + kb.y*qb.y;
    p += __shfl_down_sync(0xffffffffu, p, 4, 8);
    p += __shfl_down_sync(0xffffffffu, p, 2, 8);
    p += __shfl_down_sync(0xffffffffu, p, 1, 8);
    float att = __shfl_sync(0xffffffffu, p, 0, 8);
    float ev  = __expf(att);

    float2 ma = __half22float2(*(const __half2*)&mv.x);
    float2 mb = __half22float2(*(const __half2*)&mv.y);

    float* arow = g_agg + (size_t)(d*NN + dst)*OUTF + lane*4;
    asm volatile("red.global.add.v4.f32 [%0], {%1,%2,%3,%4};"
                 :: "l"(arow), "f"(ma.x*ev), "f"(ma.y*ev), "f"(mb.x*ev), "f"(mb.y*ev)
                 : "memory");
    if ((lane & 7) == 0)
        atomicAdd(g_den + (size_t)(d*NN + dst)*HH + (lane >> 3), ev);
}

// ---------------- node pass: gelu(agg/den) -> mma GEMM -> skip + LN ----------------
__global__ void __launch_bounds__(256, 2) node_mma_kernel(const float* __restrict__ x,
                                                          const float* __restrict__ ba,
                                                          const float* __restrict__ skip,
                                                          const float* __restrict__ lns,
                                                          const float* __restrict__ lnb,
                                                          float* __restrict__ out) {
    extern __shared__ char sm[];
    uint32_t su = smem_u32(sm);
    float* S = (float*)sm;        // reuse A hi/lo region after GEMM: [128][136] f32 = 69632B
    int tid = threadIdx.x;
    int w = tid >> 5, lane = tid & 31;
    int wm = w & 3, wn = w >> 2;

    int blk = blockIdx.x;
    int ntp = blk >= TILES;
    int tb  = blk - ntp*TILES;
    int base = tb*128; if (base > NN-128) base = NN-128;
    size_t nbase = (size_t)ntp*NN + base;

    // stage A = gelu(agg/den) -> bf16 hi/lo smem
    #pragma unroll 4
    for (int j = 0; j < 16; j++) {
        int idx = tid + j*256;
        int row = idx >> 5, c4 = idx & 31;
        size_t nrow = nbase + row;
        float4 v = ((const float4*)(g_agg + nrow*OUTF))[c4];
        float idn = 1.f / (g_den[nrow*HH + (c4 >> 3)] + 1e-16f);
        v.x *= idn; v.y *= idn; v.z *= idn; v.w *= idn;
        v.x = 0.5f*v.x*(1.f + erff(v.x*0.70710678118654752f));
        v.y = 0.5f*v.y*(1.f + erff(v.y*0.70710678118654752f));
        v.z = 0.5f*v.z*(1.f + erff(v.z*0.70710678118654752f));
        v.w = 0.5f*v.w*(1.f + erff(v.w*0.70710678118654752f));
        uint32_t hi[2], lo[2];
        split4(v, hi, lo);
        *(uint32_t*)(sm + A_HI_OFF + row*ROWB + c4*8)     = hi[0];
        *(uint32_t*)(sm + A_HI_OFF + row*ROWB + c4*8 + 4) = hi[1];
        *(uint32_t*)(sm + A_LO_OFF + row*ROWB + c4*8)     = lo[0];
        *(uint32_t*)(sm + A_LO_OFF + row*ROWB + c4*8 + 4) = lo[1];
    }
    __syncthreads();
    copy_B_half(sm, 3, ntp, 0, tid);
    __syncthreads();

    float acc[2][8][4];
    #pragma unroll
    for (int mt = 0; mt < 2; mt++)
        #pragma unroll
        for (int nt = 0; nt < 8; nt++) {
            int col = wn*64 + nt*8 + 2*(lane & 3);
            float b0 = ba[ntp*OUTF + col], b1 = ba[ntp*OUTF + col + 1];
            acc[mt][nt][0] = b0; acc[mt][nt][1] = b1;
            acc[mt][nt][2] = b0; acc[mt][nt][3] = b1;
        }
    gemm_pass1(su, w, lane, acc);
    __syncthreads();
    copy_B_half(sm, 3, ntp, 1, tid);
    __syncthreads();
    gemm_pass2(su, w, lane, acc);
    __syncthreads();   // all warps done reading A region before reuse as S

    // acc -> S [128][136] f32
    #pragma unroll
    for (int mt = 0; mt < 2; mt++)
        #pragma unroll
        for (int nt = 0; nt < 8; nt++) {
            int row = wm*32 + mt*16 + (lane >> 2);
            int col = wn*64 + nt*8 + 2*(lane & 3);
            *(float2*)(S + row*136 + col)     = make_float2(acc[mt][nt][0], acc[mt][nt][1]);
            *(float2*)(S + (row+8)*136 + col) = make_float2(acc[mt][nt][2], acc[mt][nt][3]);
        }
    __syncthreads();

    // skip blend
    float alpha = 1.f / (1.f + __expf(-skip[ntp]));
    float beta  = 1.f - alpha;
    #pragma unroll 4
    for (int i = tid; i < 128*128; i += 256) {
        int r = i >> 7, c = i & 127;
        S[r*136 + c] = alpha*S[r*136 + c] + beta*x[(nbase + r)*INF + c];
    }
    __syncthreads();

    // layernorm: warp w rows 16w..16w+15
    for (int rr = 0; rr < 16; rr++) {
        int r = w*16 + rr;
        float s1 = 0.f, s2 = 0.f;
        #pragma unroll
        for (int c = lane; c < OUTF; c += 32) { float v = S[r*136 + c]; s1 += v; s2 += v*v; }
        #pragma unroll
        for (int off = 16; off; off >>= 1) {
            s1 += __shfl_xor_sync(0xffffffffu, s1, off);
            s2 += __shfl_xor_sync(0xffffffffu, s2, off);
        }
        float mean = s1 * (1.f/OUTF);
        float var  = s2 * (1.f/OUTF) - mean*mean;
        float inv  = rsqrtf(var + 1e-5f);
        #pragma unroll
        for (int c = lane; c < OUTF; c += 32)
            out[(nbase + r)*OUTF + c] = (S[r*136 + c] - mean)*inv*lns[ntp*OUTF + c]
                                        + lnb[ntp*OUTF + c];
    }
}

// ---------------- launch ----------------
extern "C" void kernel_launch(void* const* d_in, const int* in_sizes, int n_in,
                              void* d_out, int out_size) {
    const float* x     = (const float*)d_in[0];
    const int*   ei    = (const int*)  d_in[1];
    const float* Wk    = (const float*)d_in[2];
    const float* bk    = (const float*)d_in[3];
    const float* Wq    = (const float*)d_in[4];
    const float* bq    = (const float*)d_in[5];
    const float* Wm    = (const float*)d_in[6];
    const float* bm    = (const float*)d_in[7];
    const float* Wa    = (const float*)d_in[8];
    const float* ba    = (const float*)d_in[9];
    const float* w_att = (const float*)d_in[10];
    const float* w_msg = (const float*)d_in[11];
    const float* mu    = (const float*)d_in[12];
    const float* skip  = (const float*)d_in[13];
    const float* lns   = (const float*)d_in[14];
    const float* lnb   = (const float*)d_in[15];
    float* out = (float*)d_out;

    cudaFuncSetAttribute(proj_mma_kernel, cudaFuncAttributeMaxDynamicSharedMemorySize, SMEM_TOT);
    cudaFuncSetAttribute(node_mma_kernel, cudaFuncAttributeMaxDynamicSharedMemorySize, SMEM_TOT);

    prep_fold<<<256, 256>>>(Wk, bk, Wm, bm, w_att, w_msg, mu);
    prep_pack<<<512, 256>>>(Wq, Wa);
    zero_kernel<<<50000, 256>>>();
    proj_mma_kernel<<<2*TILES, 256, SMEM_TOT>>>(x, bq);
    edge_kernel<<<(2*EE*32)/256, 256>>>(ei);
    node_mma_kernel<<<2*TILES, 256, SMEM_TOT>>>(x, ba, skip, lns, lnb, out);
}